// round 3
// baseline (speedup 1.0000x reference)
#include <cuda_runtime.h>
#include <math.h>

#define B_  4
#define T_  2048
#define C_  1024
#define H_  16
#define N_  64
#define Q_  256
#define NC_ 8
#define BT_ (B_*T_)

// ---------------- scratch (single __device__ global, no allocations) ----------------
static constexpr size_t SZ_MAT  = (size_t)BT_ * C_;        // 8388608
static constexpr size_t SZ_BHT  = (size_t)B_ * H_ * T_;    // 131072
static constexpr size_t SZ_KV   = (size_t)B_ * H_ * NC_ * N_ * N_; // 2097152

static constexpr size_t OFF_XX     = 0;
static constexpr size_t OFF_XXX    = OFF_XX     + SZ_MAT;
static constexpr size_t OFF_M1     = OFF_XXX    + SZ_MAT;            // BT*128
static constexpr size_t OFF_XW     = OFF_M1     + (size_t)BT_*128;
static constexpr size_t OFF_XK     = OFF_XW     + SZ_MAT;
static constexpr size_t OFF_XV     = OFF_XK     + SZ_MAT;
static constexpr size_t OFF_XR     = OFF_XV     + SZ_MAT;
static constexpr size_t OFF_R      = OFF_XR     + SZ_MAT;
static constexpr size_t OFF_K      = OFF_R      + SZ_MAT;
static constexpr size_t OFF_V      = OFF_K      + SZ_MAT;
static constexpr size_t OFF_W1MID  = OFF_V      + SZ_MAT;            // BT*64
static constexpr size_t OFF_DW2M   = OFF_W1MID  + (size_t)BT_*64;    // 1024
static constexpr size_t OFF_MTD    = OFF_DW2M   + 1024;              // 64 (padded)
static constexpr size_t OFF_WHEAD  = OFF_MTD    + 64;                // B*H*T
static constexpr size_t OFF_CC     = OFF_WHEAD  + SZ_BHT;
static constexpr size_t OFF_CQE    = OFF_CC     + SZ_BHT;
static constexpr size_t OFF_WINTRA = OFF_CQE    + SZ_BHT;
static constexpr size_t OFF_WINTER = OFF_WINTRA + SZ_BHT;
static constexpr size_t OFF_WS     = OFF_WINTER + SZ_BHT;            // 512
static constexpr size_t OFF_KVB    = OFF_WS     + 512;
static constexpr size_t OFF_STATES = OFF_KVB    + SZ_KV;
static constexpr size_t OFF_Y      = OFF_STATES + SZ_KV;
static constexpr size_t OFF_YN     = OFF_Y      + SZ_MAT;
static constexpr size_t TOTAL_SCRATCH = OFF_YN + SZ_MAT;

__device__ float g_scratch[TOTAL_SCRATCH];

// ---------------- 1. time shift + xxx ----------------
__global__ void prepass_kernel(const float* __restrict__ x, const float* __restrict__ tmx,
                               float* __restrict__ xx, float* __restrict__ xxx)
{
    int bt = blockIdx.x, tid = threadIdx.x;
    int t = bt & (T_ - 1);
    size_t off = (size_t)bt * C_ + tid * 4;
    float4 xv = *(const float4*)(x + off);
    float4 pv = make_float4(0.f, 0.f, 0.f, 0.f);
    if (t > 0) pv = *(const float4*)(x + off - C_);
    float4 d;
    d.x = pv.x - xv.x; d.y = pv.y - xv.y; d.z = pv.z - xv.z; d.w = pv.w - xv.w;
    float4 tm = *(const float4*)(tmx + tid * 4);
    float4 o;
    o.x = xv.x + d.x * tm.x; o.y = xv.y + d.y * tm.y;
    o.z = xv.z + d.z * tm.z; o.w = xv.w + d.w * tm.w;
    *(float4*)(xx + off)  = d;
    *(float4*)(xxx + off) = o;
}

// ---------------- generic SGEMM 128x128x8, 8x8 per thread, optional tanh ----------------
__global__ __launch_bounds__(256) void sgemm_kernel(
    const float* __restrict__ A, const float* __restrict__ B, float* __restrict__ C,
    int M, int N, int K, int act)
{
    __shared__ float As[8][128];
    __shared__ float Bs[8][128];
    const int tid = threadIdx.x;
    const int bx = blockIdx.x, by = blockIdx.y;
    const int ty = (tid >> 4) * 8;
    const int tx = (tid & 15) * 8;
    const int aRow = tid >> 1;
    const int aCol = (tid & 1) * 4;
    const int bRow = tid >> 5;
    const int bCol = (tid & 31) * 4;
    const float* Ap = A + (size_t)(by * 128 + aRow) * K + aCol;
    const bool bValid = (bx * 128 + bCol) < N;
    const float* Bp = B + (size_t)bRow * N + bx * 128 + bCol;

    float acc[8][8];
    #pragma unroll
    for (int i = 0; i < 8; i++)
        #pragma unroll
        for (int j = 0; j < 8; j++) acc[i][j] = 0.f;

    for (int k0 = 0; k0 < K; k0 += 8) {
        float4 a4 = *(const float4*)(Ap + k0);
        As[aCol + 0][aRow] = a4.x; As[aCol + 1][aRow] = a4.y;
        As[aCol + 2][aRow] = a4.z; As[aCol + 3][aRow] = a4.w;
        float4 b4 = bValid ? *(const float4*)(Bp + (size_t)k0 * N)
                           : make_float4(0.f, 0.f, 0.f, 0.f);
        *(float4*)&Bs[bRow][bCol] = b4;
        __syncthreads();
        #pragma unroll
        for (int kk = 0; kk < 8; kk++) {
            float ar[8], br[8];
            #pragma unroll
            for (int i = 0; i < 8; i++) ar[i] = As[kk][ty + i];
            #pragma unroll
            for (int j = 0; j < 8; j++) br[j] = Bs[kk][tx + j];
            #pragma unroll
            for (int i = 0; i < 8; i++)
                #pragma unroll
                for (int j = 0; j < 8; j++) acc[i][j] += ar[i] * br[j];
        }
        __syncthreads();
    }

    #pragma unroll
    for (int i = 0; i < 8; i++) {
        size_t crow = (size_t)(by * 128 + ty + i) * N;
        int ccol = bx * 128 + tx;
        #pragma unroll
        for (int j = 0; j < 8; j += 4) {
            if (ccol + j < N) {
                float4 o;
                o.x = act ? tanhf(acc[i][j + 0]) : acc[i][j + 0];
                o.y = act ? tanhf(acc[i][j + 1]) : acc[i][j + 1];
                o.z = act ? tanhf(acc[i][j + 2]) : acc[i][j + 2];
                o.w = act ? tanhf(acc[i][j + 3]) : acc[i][j + 3];
                *(float4*)(C + crow + ccol + j) = o;
            }
        }
    }
}

// ---------------- 3. fused token-mix: mf = m1[:,f*32:]@w2[f] ; x? = x + xx*(tm + mf) ----------------
__global__ __launch_bounds__(256) void mix_gemm_kernel(
    const float* __restrict__ m1, const float* __restrict__ w2,
    const float* __restrict__ x, const float* __restrict__ xx,
    const float* __restrict__ tmw, const float* __restrict__ tmk,
    const float* __restrict__ tmv, const float* __restrict__ tmr,
    float* __restrict__ xw, float* __restrict__ xk,
    float* __restrict__ xv, float* __restrict__ xr)
{
    __shared__ float As[32][64];
    __shared__ float Bs[32][128];
    int tid = threadIdx.x;
    int f = blockIdx.z;
    int row0 = blockIdx.y * 64;
    int col0 = blockIdx.x * 128;

    #pragma unroll
    for (int it = 0; it < 2; it++) {
        int s = tid + 256 * it;
        int rr = s >> 3, d4 = (s & 7) * 4;
        float4 t = *(const float4*)(m1 + (size_t)(row0 + rr) * 128 + f * 32 + d4);
        As[d4 + 0][rr] = t.x; As[d4 + 1][rr] = t.y;
        As[d4 + 2][rr] = t.z; As[d4 + 3][rr] = t.w;
    }
    #pragma unroll
    for (int it = 0; it < 4; it++) {
        int s = tid + 256 * it;
        int d = s >> 5, c4 = (s & 31) * 4;
        *(float4*)&Bs[d][c4] = *(const float4*)(w2 + ((size_t)f * 32 + d) * C_ + col0 + c4);
    }
    __syncthreads();

    int ty = (tid >> 4) * 4, tx = (tid & 15) * 8;
    float acc[4][8];
    #pragma unroll
    for (int i = 0; i < 4; i++)
        #pragma unroll
        for (int j = 0; j < 8; j++) acc[i][j] = 0.f;

    #pragma unroll
    for (int d = 0; d < 32; d++) {
        float ar[4], br[8];
        #pragma unroll
        for (int i = 0; i < 4; i++) ar[i] = As[d][ty + i];
        #pragma unroll
        for (int j = 0; j < 8; j++) br[j] = Bs[d][tx + j];
        #pragma unroll
        for (int i = 0; i < 4; i++)
            #pragma unroll
            for (int j = 0; j < 8; j++) acc[i][j] += ar[i] * br[j];
    }

    const float* tm = (f == 0) ? tmw : (f == 1) ? tmk : (f == 2) ? tmv : tmr;
    float* out      = (f == 0) ? xw  : (f == 1) ? xk  : (f == 2) ? xv  : xr;

    #pragma unroll
    for (int i = 0; i < 4; i++) {
        size_t rowi = (size_t)(row0 + ty + i) * C_;
        #pragma unroll
        for (int j = 0; j < 8; j += 4) {
            int cidx = col0 + tx + j;
            float4 xv4 = *(const float4*)(x + rowi + cidx);
            float4 dx4 = *(const float4*)(xx + rowi + cidx);
            float4 tm4 = *(const float4*)(tm + cidx);
            float4 o;
            o.x = xv4.x + dx4.x * (tm4.x + acc[i][j + 0]);
            o.y = xv4.y + dx4.y * (tm4.y + acc[i][j + 1]);
            o.z = xv4.z + dx4.z * (tm4.z + acc[i][j + 2]);
            o.w = xv4.w + dx4.w * (tm4.w + acc[i][j + 3]);
            *(float4*)(out + rowi + cidx) = o;
        }
    }
}

// ---------------- 4. decay head-mean precompute: dw2m[j][h], mtd[h] ----------------
__global__ void wprep_kernel(const float* __restrict__ dw2, const float* __restrict__ td,
                             float* __restrict__ dw2m, float* __restrict__ mtd)
{
    int tid = threadIdx.x;             // 1024 threads
    int j = tid >> 4, h = tid & 15;
    float s = 0.f;
    #pragma unroll
    for (int n = 0; n < 64; n++) s += dw2[(size_t)j * C_ + h * 64 + n];
    dw2m[j * 16 + h] = s * (1.f / 64.f);
    if (tid < 16) {
        float s2 = 0.f;
        #pragma unroll
        for (int n = 0; n < 64; n++) s2 += td[tid * 64 + n];
        mtd[tid] = s2 * (1.f / 64.f);
    }
}

// ---------------- 5. whead[b,h,t] = mtd[h] + w1mid[bt,:]·dw2m[:,h] ----------------
__global__ void whead_kernel(const float* __restrict__ w1mid, const float* __restrict__ dw2m,
                             const float* __restrict__ mtd, float* __restrict__ whead)
{
    __shared__ float rows[16][64];
    __shared__ float dsh[1024];
    __shared__ float msh[16];
    int tid = threadIdx.x;
    int bt0 = blockIdx.x * 16;
    {
        int rr = tid >> 4, n4 = (tid & 15) * 4;
        float4 t = *(const float4*)(w1mid + (size_t)(bt0 + rr) * 64 + n4);
        rows[rr][n4] = t.x; rows[rr][n4 + 1] = t.y;
        rows[rr][n4 + 2] = t.z; rows[rr][n4 + 3] = t.w;
    }
    #pragma unroll
    for (int it = 0; it < 4; it++) dsh[tid + 256 * it] = dw2m[tid + 256 * it];
    if (tid < 16) msh[tid] = mtd[tid];
    __syncthreads();
    int rr = tid >> 4, h = tid & 15;
    float s = msh[h];
    #pragma unroll
    for (int j = 0; j < 64; j++) s += rows[rr][j] * dsh[j * 16 + h];
    int bt = bt0 + rr;
    int b = bt >> 11;
    int t = bt & (T_ - 1);
    whead[((size_t)(b * H_ + h)) * T_ + t] = s;
}

// ---------------- 6. per-chunk cumsum / decay factors ----------------
__global__ void chunkscan_kernel(const float* __restrict__ whead, float* __restrict__ cc,
                                 float* __restrict__ cqe, float* __restrict__ wintra,
                                 float* __restrict__ winter, float* __restrict__ ws)
{
    int blk = blockIdx.x;              // bh*NC + c
    int tid = threadIdx.x;             // 256 = Q
    int bh = blk >> 3, c = blk & 7;
    size_t idx = (size_t)bh * T_ + c * Q_ + tid;
    float wl = -__expf(whead[idx]);
    float v = wl;
    int lane = tid & 31, warp = tid >> 5;
    #pragma unroll
    for (int o = 1; o < 32; o <<= 1) {
        float n = __shfl_up_sync(0xffffffffu, v, o);
        if (lane >= o) v += n;
    }
    __shared__ float wsum[8], woff[8], stot;
    if (lane == 31) wsum[warp] = v;
    __syncthreads();
    if (tid == 0) {
        float run = 0.f;
        for (int w = 0; w < 8; w++) { woff[w] = run; run += wsum[w]; }
        stot = run;
    }
    __syncthreads();
    float ccv = v + woff[warp];
    float tot = stot;
    float e = ccv - wl;                // exclusive cumsum (log)
    cc[idx] = ccv;
    cqe[idx] = e;
    wintra[idx] = __expf(e);
    winter[idx] = __expf(tot - ccv);
    if (tid == 0) ws[blk] = __expf(tot);
}

// ---------------- 7. kv[b,h,c] = (kk*w_inter)^T @ vv   (N x N) ----------------
__global__ void kv_kernel(const float* __restrict__ k, const float* __restrict__ v,
                          const float* __restrict__ winter, float* __restrict__ kvbuf)
{
    __shared__ float a_s[64][64];
    __shared__ float b_s[64][64];
    int blk = blockIdx.x, tid = threadIdx.x;
    int c = blk & 7, bh = blk >> 3, h = bh & 15, b = bh >> 4;
    size_t rowbase = ((size_t)(b * T_) + c * Q_) * C_ + h * 64;
    size_t wbase = (size_t)bh * T_ + c * Q_;
    int n = tid & 63, mg = tid >> 6;
    float acc[16];
    #pragma unroll
    for (int j = 0; j < 16; j++) acc[j] = 0.f;

    for (int q0 = 0; q0 < Q_; q0 += 64) {
        __syncthreads();
        #pragma unroll
        for (int it = 0; it < 4; it++) {
            int s = tid + 256 * it;
            int qq = s >> 4, n4 = (s & 15) * 4;
            float wI = winter[wbase + q0 + qq];
            float4 kk4 = *(const float4*)(k + rowbase + (size_t)(q0 + qq) * C_ + n4);
            a_s[qq][n4 + 0] = kk4.x * wI; a_s[qq][n4 + 1] = kk4.y * wI;
            a_s[qq][n4 + 2] = kk4.z * wI; a_s[qq][n4 + 3] = kk4.w * wI;
            float4 vv4 = *(const float4*)(v + rowbase + (size_t)(q0 + qq) * C_ + n4);
            *(float4*)&b_s[qq][n4] = vv4;
        }
        __syncthreads();
        for (int qq = 0; qq < 64; qq++) {
            float av = a_s[qq][n];
            #pragma unroll
            for (int j = 0; j < 16; j++) acc[j] += av * b_s[qq][mg * 16 + j];
        }
    }
    float* out = kvbuf + (size_t)blk * 4096 + (size_t)n * 64 + mg * 16;
    #pragma unroll
    for (int j = 0; j < 16; j += 4) {
        float4 o; o.x = acc[j]; o.y = acc[j + 1]; o.z = acc[j + 2]; o.w = acc[j + 3];
        *(float4*)(out + j) = o;
    }
}

// ---------------- 8. state scan over chunks (emit before update) ----------------
__global__ void state_scan_kernel(const float* __restrict__ kvbuf, const float* __restrict__ ws,
                                  float* __restrict__ states)
{
    int bh = blockIdx.x, tid = threadIdx.x;
    float4 st[4];
    #pragma unroll
    for (int u = 0; u < 4; u++) st[u] = make_float4(0.f, 0.f, 0.f, 0.f);
    for (int c = 0; c < NC_; c++) {
        size_t base = ((size_t)bh * NC_ + c) * 4096 + (size_t)tid * 16;
        float w = ws[bh * NC_ + c];
        #pragma unroll
        for (int u = 0; u < 4; u++) {
            *(float4*)(states + base + u * 4) = st[u];
            float4 kv4 = *(const float4*)(kvbuf + base + u * 4);
            st[u].x = w * st[u].x + kv4.x;
            st[u].y = w * st[u].y + kv4.y;
            st[u].z = w * st[u].z + kv4.z;
            st[u].w = w * st[u].w + kv4.w;
        }
    }
}

// ---------------- 9. chunked attention: inter + intra + diag ----------------
static constexpr int KROW = 68;   // padded row stride (floats), keeps float4 alignment
static constexpr size_t ATTN_SMEM = (2 * 256 * KROW + 4096 + 256 + 64) * sizeof(float);

__global__ __launch_bounds__(256) void attn_kernel(
    const float* __restrict__ r, const float* __restrict__ k, const float* __restrict__ v,
    const float* __restrict__ cc, const float* __restrict__ cqe, const float* __restrict__ wintra,
    const float* __restrict__ states, const float* __restrict__ faaaa, float* __restrict__ y)
{
    extern __shared__ float smem[];
    float* kk_s = smem;
    float* vv_s = smem + 256 * KROW;
    float* st_s = smem + 2 * 256 * KROW;
    float* cc_s = st_s + 4096;
    float* fa_s = cc_s + 256;

    int blk = blockIdx.x, tid = threadIdx.x;
    int c = blk & 7, bh = blk >> 3, h = bh & 15, b = bh >> 4;
    size_t rowbase = ((size_t)(b * T_) + c * Q_) * C_ + h * 64;
    size_t wbase = (size_t)bh * T_ + c * Q_;

    #pragma unroll
    for (int it = 0; it < 16; it++) {
        int s = tid + 256 * it;
        int qq = s >> 4, n4 = (s & 15) * 4;
        *(float4*)(kk_s + qq * KROW + n4) = *(const float4*)(k + rowbase + (size_t)qq * C_ + n4);
        *(float4*)(vv_s + qq * KROW + n4) = *(const float4*)(v + rowbase + (size_t)qq * C_ + n4);
    }
    #pragma unroll
    for (int it = 0; it < 4; it++) {
        int s4 = (tid + 256 * it) * 4;
        *(float4*)(st_s + s4) = *(const float4*)(states + (size_t)blk * 4096 + s4);
    }
    cc_s[tid] = cc[wbase + tid];
    if (tid < 64) fa_s[tid] = faaaa[h * 64 + tid];
    __syncthreads();

    // SMSP-balanced q permutation: warps w and w+4 share an SMSP -> pair long+short rows
    int wslot = tid >> 5;
    int pq = (wslot & 1) ? (7 - (wslot >> 1)) : (wslot >> 1);
    int q = pq * 32 + (tid & 31);

    float r_[64];
    #pragma unroll
    for (int n4 = 0; n4 < 64; n4 += 4) {
        float4 t = *(const float4*)(r + rowbase + (size_t)q * C_ + n4);
        r_[n4] = t.x; r_[n4 + 1] = t.y; r_[n4 + 2] = t.z; r_[n4 + 3] = t.w;
    }
    float cqeq = cqe[wbase + q];
    float wi = wintra[wbase + q];
    float acc[64];
    #pragma unroll
    for (int m = 0; m < 64; m++) acc[m] = 0.f;

    // intra (strict-lower masked scores @ vv)
    for (int kk = 0; kk < q; kk++) {
        const float* krow = kk_s + kk * KROW;
        float s0 = 0.f, s1 = 0.f, s2 = 0.f, s3 = 0.f;
        #pragma unroll
        for (int n = 0; n < 64; n += 4) {
            s0 += r_[n + 0] * krow[n + 0];
            s1 += r_[n + 1] * krow[n + 1];
            s2 += r_[n + 2] * krow[n + 2];
            s3 += r_[n + 3] * krow[n + 3];
        }
        float smv = ((s0 + s1) + (s2 + s3)) * __expf(cqeq - cc_s[kk]);
        const float* vrow = vv_s + kk * KROW;
        #pragma unroll
        for (int m = 0; m < 64; m++) acc[m] += smv * vrow[m];
    }
    // inter ((rr*w_intra) @ state)
    for (int n = 0; n < 64; n++) {
        float rn = r_[n] * wi;
        const float* srow = st_s + n * 64;
        #pragma unroll
        for (int m = 0; m < 64; m++) acc[m] += rn * srow[m];
    }
    // diag
    float d = 0.f;
    const float* krq = kk_s + q * KROW;
    #pragma unroll
    for (int n = 0; n < 64; n++) d += r_[n] * fa_s[n] * krq[n];
    const float* vrq = vv_s + q * KROW;
    #pragma unroll
    for (int m = 0; m < 64; m++) acc[m] += d * vrq[m];

    float* yp = y + rowbase + (size_t)q * C_;
    #pragma unroll
    for (int m = 0; m < 64; m += 4) {
        float4 o; o.x = acc[m]; o.y = acc[m + 1]; o.z = acc[m + 2]; o.w = acc[m + 3];
        *(float4*)(yp + m) = o;
    }
}

// ---------------- 10. layernorm ----------------
__global__ void ln_kernel(const float* __restrict__ yin, const float* __restrict__ g,
                          const float* __restrict__ bia, float* __restrict__ yout)
{
    int row = blockIdx.x, tid = threadIdx.x;
    const float4* in = (const float4*)(yin + (size_t)row * C_);
    float4 v = in[tid];
    float s = v.x + v.y + v.z + v.w;
    float s2 = v.x * v.x + v.y * v.y + v.z * v.z + v.w * v.w;
    #pragma unroll
    for (int o = 16; o > 0; o >>= 1) {
        s  += __shfl_down_sync(0xffffffffu, s, o);
        s2 += __shfl_down_sync(0xffffffffu, s2, o);
    }
    __shared__ float rs[8], rs2[8];
    __shared__ float smu, srstd;
    if ((tid & 31) == 0) { rs[tid >> 5] = s; rs2[tid >> 5] = s2; }
    __syncthreads();
    if (tid == 0) {
        float a = 0.f, bb = 0.f;
        for (int w = 0; w < 8; w++) { a += rs[w]; bb += rs2[w]; }
        float mu = a * (1.f / C_);
        float var = bb * (1.f / C_) - mu * mu;
        smu = mu; srstd = rsqrtf(var + 1e-5f);
    }
    __syncthreads();
    float mu = smu, rstd = srstd;
    float4 gg = ((const float4*)g)[tid];
    float4 bb = ((const float4*)bia)[tid];
    float4 o;
    o.x = (v.x - mu) * rstd * gg.x + bb.x;
    o.y = (v.y - mu) * rstd * gg.y + bb.y;
    o.z = (v.z - mu) * rstd * gg.z + bb.z;
    o.w = (v.w - mu) * rstd * gg.w + bb.w;
    ((float4*)(yout + (size_t)row * C_))[tid] = o;
}

// ---------------- launch ----------------
extern "C" void kernel_launch(void* const* d_in, const int* in_sizes, int n_in,
                              void* d_out, int out_size)
{
    const float* x       = (const float*)d_in[0];
    const float* tmx     = (const float*)d_in[1];
    const float* tmw     = (const float*)d_in[2];
    const float* tmk     = (const float*)d_in[3];
    const float* tmv     = (const float*)d_in[4];
    const float* tmr     = (const float*)d_in[5];
    const float* maa_w1  = (const float*)d_in[6];
    const float* maa_w2  = (const float*)d_in[7];
    const float* dec_w1  = (const float*)d_in[8];
    const float* dec_w2  = (const float*)d_in[9];
    const float* tdecay  = (const float*)d_in[10];
    const float* faaaa   = (const float*)d_in[11];
    const float* Wr      = (const float*)d_in[12];
    const float* Wk      = (const float*)d_in[13];
    const float* Wv      = (const float*)d_in[14];
    const float* Wo      = (const float*)d_in[15];
    const float* ln_g    = (const float*)d_in[16];
    const float* ln_b    = (const float*)d_in[17];
    float* out = (float*)d_out;

    float* base = nullptr;
    cudaGetSymbolAddress((void**)&base, g_scratch);
    float* xx     = base + OFF_XX;
    float* xxx    = base + OFF_XXX;
    float* m1     = base + OFF_M1;
    float* xw     = base + OFF_XW;
    float* xk     = base + OFF_XK;
    float* xv     = base + OFF_XV;
    float* xr     = base + OFF_XR;
    float* rbuf   = base + OFF_R;
    float* kbuf   = base + OFF_K;
    float* vbuf   = base + OFF_V;
    float* w1mid  = base + OFF_W1MID;
    float* dw2m   = base + OFF_DW2M;
    float* mtd    = base + OFF_MTD;
    float* whead  = base + OFF_WHEAD;
    float* ccb    = base + OFF_CC;
    float* cqeb   = base + OFF_CQE;
    float* wintra = base + OFF_WINTRA;
    float* winter = base + OFF_WINTER;
    float* wsb    = base + OFF_WS;
    float* kvbuf  = base + OFF_KVB;
    float* states = base + OFF_STATES;
    float* ybuf   = base + OFF_Y;
    float* ynbuf  = base + OFF_YN;

    cudaFuncSetAttribute(attn_kernel, cudaFuncAttributeMaxDynamicSharedMemorySize,
                         (int)ATTN_SMEM);

    prepass_kernel<<<BT_, 256>>>(x, tmx, xx, xxx);
    sgemm_kernel<<<dim3(1, 64), 256>>>(xxx, maa_w1, m1, BT_, 128, 1024, 1);
    mix_gemm_kernel<<<dim3(8, 128, 4), 256>>>(m1, maa_w2, x, xx,
                                              tmw, tmk, tmv, tmr, xw, xk, xv, xr);
    sgemm_kernel<<<dim3(8, 64), 256>>>(xr, Wr, rbuf, BT_, 1024, 1024, 0);
    sgemm_kernel<<<dim3(8, 64), 256>>>(xk, Wk, kbuf, BT_, 1024, 1024, 0);
    sgemm_kernel<<<dim3(8, 64), 256>>>(xv, Wv, vbuf, BT_, 1024, 1024, 0);
    sgemm_kernel<<<dim3(1, 64), 256>>>(xw, dec_w1, w1mid, BT_, 64, 1024, 1);
    wprep_kernel<<<1, 1024>>>(dec_w2, tdecay, dw2m, mtd);
    whead_kernel<<<BT_ / 16, 256>>>(w1mid, dw2m, mtd, whead);
    chunkscan_kernel<<<B_ * H_ * NC_, 256>>>(whead, ccb, cqeb, wintra, winter, wsb);
    kv_kernel<<<B_ * H_ * NC_, 256>>>(kbuf, vbuf, winter, kvbuf);
    state_scan_kernel<<<B_ * H_, 256>>>(kvbuf, wsb, states);
    attn_kernel<<<B_ * H_ * NC_, 256, ATTN_SMEM>>>(rbuf, kbuf, vbuf, ccb, cqeb, wintra,
                                                   states, faaaa, ybuf);
    ln_kernel<<<BT_, 256>>>(ybuf, ln_g, ln_b, ynbuf);
    sgemm_kernel<<<dim3(8, 64), 256>>>(ynbuf, Wo, out, BT_, 1024, 1024, 0);
}